// round 6
// baseline (speedup 1.0000x reference)
#include <cuda_runtime.h>
#include <cuda_bf16.h>
#include <cstdint>

#define BDIM    1024
#define TSEQ    2048
#define MROWS   8192
#define NRELS   256        // padded rel rows (129 -> 256, zero-filled)
#define KCHUNKS 16         // 1024 / 64

// ---------------------------------------------------------------------------
// Scratch (__device__ globals; no allocations allowed)
// ---------------------------------------------------------------------------
__device__ __nv_bfloat16 g_rhi[(size_t)MROWS * BDIM];
__device__ __nv_bfloat16 g_rlo[(size_t)MROWS * BDIM];
__device__ __nv_bfloat16 g_qhi[2ull * MROWS * BDIM];
__device__ __nv_bfloat16 g_qlo[2ull * MROWS * BDIM];
__device__ __nv_bfloat16 g_khi[2ull * MROWS * BDIM];
__device__ __nv_bfloat16 g_klo[2ull * MROWS * BDIM];
__device__ __nv_bfloat16 g_wth[4ull * BDIM * BDIM];
__device__ __nv_bfloat16 g_wtl[4ull * BDIM * BDIM];
__device__ __nv_bfloat16 g_relh[2ull * NRELS * BDIM];
__device__ __nv_bfloat16 g_rell[2ull * NRELS * BDIM];
__device__ float         g_qr  [2ull * MROWS * NRELS];

// ---------------------------------------------------------------------------
// Helpers (baseline PTX only: cp.async / ldmatrix / mma.sync)
// ---------------------------------------------------------------------------
__device__ __forceinline__ uint32_t smem_u32(const void* p) {
    uint32_t a;
    asm("{ .reg .u64 t; cvta.to.shared.u64 t, %1; cvt.u32.u64 %0, t; }"
        : "=r"(a) : "l"(p));
    return a;
}

__device__ __forceinline__ void cp_async16(uint32_t dst, const void* src) {
    asm volatile("cp.async.cg.shared.global [%0], [%1], 16;\n" :: "r"(dst), "l"(src));
}
#define CP_COMMIT() asm volatile("cp.async.commit_group;\n" ::: "memory")
#define CP_WAIT1()  asm volatile("cp.async.wait_group 1;\n" ::: "memory")
#define CP_WAIT0()  asm volatile("cp.async.wait_group 0;\n" ::: "memory")

__device__ __forceinline__ void ldsm4(uint32_t addr, uint32_t* r) {
    asm volatile("ldmatrix.sync.aligned.m8n8.x4.shared.b16 {%0,%1,%2,%3}, [%4];"
        : "=r"(r[0]), "=r"(r[1]), "=r"(r[2]), "=r"(r[3]) : "r"(addr));
}

__device__ __forceinline__ void mma_bf16(float* c, const uint32_t* a,
                                         uint32_t b0, uint32_t b1) {
    asm volatile(
        "mma.sync.aligned.m16n8k16.row.col.f32.bf16.bf16.f32 "
        "{%0,%1,%2,%3}, {%4,%5,%6,%7}, {%8,%9}, {%0,%1,%2,%3};"
        : "+f"(c[0]), "+f"(c[1]), "+f"(c[2]), "+f"(c[3])
        : "r"(a[0]), "r"(a[1]), "r"(a[2]), "r"(a[3]), "r"(b0), "r"(b1));
}

__device__ __forceinline__ void split2(float v, __nv_bfloat16& h, __nv_bfloat16& l) {
    h = __float2bfloat16(v);
    l = __float2bfloat16(v - __bfloat162float(h));
}

// ---------------------------------------------------------------------------
// Conversion kernels (merged launches)
// ---------------------------------------------------------------------------
__global__ void split_repre(const float* __restrict__ in) {
    const int n4 = MROWS * BDIM / 4;
    for (int i = blockIdx.x * blockDim.x + threadIdx.x; i < n4;
         i += gridDim.x * blockDim.x) {
        float4 v = reinterpret_cast<const float4*>(in)[i];
        __nv_bfloat16 h0, h1, h2, h3, l0, l1, l2, l3;
        split2(v.x, h0, l0); split2(v.y, h1, l1);
        split2(v.z, h2, l2); split2(v.w, h3, l3);
        reinterpret_cast<__nv_bfloat162*>(g_rhi)[i * 2 + 0] = __halves2bfloat162(h0, h1);
        reinterpret_cast<__nv_bfloat162*>(g_rhi)[i * 2 + 1] = __halves2bfloat162(h2, h3);
        reinterpret_cast<__nv_bfloat162*>(g_rlo)[i * 2 + 0] = __halves2bfloat162(l0, l1);
        reinterpret_cast<__nv_bfloat162*>(g_rlo)[i * 2 + 1] = __halves2bfloat162(l2, l3);
    }
}

// Both heads in one launch. idx in [0, 2*NRELS*BDIM)
__global__ void relpad_kernel(const float* __restrict__ rel0,
                              const float* __restrict__ rel1) {
    const int idx  = blockIdx.x * 256 + threadIdx.x;
    const int head = idx >> 18;                    // NRELS*BDIM = 2^18
    const int rem  = idx & 0x3FFFF;
    const int r = rem >> 10, c = rem & 1023;
    const float* rel = head ? rel1 : rel0;
    float v = (r < 129) ? rel[r * BDIM + c] : 0.0f;
    __nv_bfloat16 h, l; split2(v, h, l);
    g_relh[idx] = h;
    g_rell[idx] = l;
}

// All 4 weights in one launch (z = widx). block(32,8), grid(32,32,4)
__global__ void transpose_split(const float* __restrict__ W0, const float* __restrict__ W1,
                                const float* __restrict__ W2, const float* __restrict__ W3) {
    __shared__ float t[32][33];
    const int widx = blockIdx.z;
    const float* W = (widx == 0) ? W0 : (widx == 1) ? W1 : (widx == 2) ? W2 : W3;
    const int n0 = blockIdx.x * 32, k0 = blockIdx.y * 32;
    for (int i = threadIdx.y; i < 32; i += 8)
        t[i][threadIdx.x] = W[(size_t)(k0 + i) * BDIM + n0 + threadIdx.x];
    __syncthreads();
    __nv_bfloat16* th = g_wth + (size_t)widx * BDIM * BDIM;
    __nv_bfloat16* tl = g_wtl + (size_t)widx * BDIM * BDIM;
    for (int i = threadIdx.y; i < 32; i += 8) {
        float v = t[threadIdx.x][i];
        __nv_bfloat16 h, l; split2(v, h, l);
        th[(size_t)(n0 + i) * BDIM + k0 + threadIdx.x] = h;
        tl[(size_t)(n0 + i) * BDIM + k0 + threadIdx.x] = l;
    }
}

// ---------------------------------------------------------------------------
// 128x128 split-bf16 HMMA GEMM (proj + qr).
// Stage (64KB): Ah@0  Al@16K  Bh@32K  Bl@48K ; each [128 rows][64 bf16], SW128.
// ---------------------------------------------------------------------------
#define STAGE1 65536

__device__ __forceinline__ void load_stage128(
    const __nv_bfloat16* Ah, const __nv_bfloat16* Al,
    const __nv_bfloat16* Bh, const __nv_bfloat16* Bl,
    size_t kelem, uint32_t base, int tid)
{
    const __nv_bfloat16* srcs[4] = {Ah + kelem, Al + kelem, Bh + kelem, Bl + kelem};
    #pragma unroll
    for (int m = 0; m < 4; ++m) {
        const char* s = (const char*)srcs[m];
        const uint32_t b = base + m * 16384;
        #pragma unroll
        for (int it = 0; it < 4; ++it) {
            const int t = tid + it * 256;
            const int r = t >> 3, c = t & 7;
            const uint32_t off = (uint32_t)(r * 128 + c * 16);
            cp_async16(b + (off ^ ((off >> 3) & 0x70)),
                       s + (size_t)r * (BDIM * 2) + c * 16);
        }
    }
}

// MODE 0: proj (merged: widx = blockIdx.x >> 3)   MODE 1: qr (head = blockIdx.z)
template<int MODE>
__global__ __launch_bounds__(256, 1)
void gemm128(const float* __restrict__ b0, const float* __restrict__ b1,
             const float* __restrict__ b2, const float* __restrict__ b3)
{
    extern __shared__ __align__(1024) char smem[];
    const uint32_t sb = smem_u32(smem);
    const int tid  = threadIdx.x;
    const int wid  = tid >> 5;
    const int lane = tid & 31;
    const int warp_m = wid >> 2;       // 0..1
    const int warp_n = wid & 3;        // 0..3

    const __nv_bfloat16 *Ah, *Al, *Bh, *Bl;
    int widx = 0, head = 0, bxn = 0;
    if (MODE == 0) {
        widx = blockIdx.x >> 3;  bxn = blockIdx.x & 7;
        head = widx >> 1;
        const size_t ab = (size_t)blockIdx.y * 128 * BDIM;
        Ah = g_rhi + ab;  Al = g_rlo + ab;
        const size_t bb = (size_t)widx * BDIM * BDIM + (size_t)bxn * 128 * BDIM;
        Bh = g_wth + bb;  Bl = g_wtl + bb;
    } else {
        head = blockIdx.z;
        const size_t ab = ((size_t)head * MROWS + (size_t)blockIdx.y * 128) * BDIM;
        Ah = g_qhi + ab;  Al = g_qlo + ab;
        const size_t bb = ((size_t)head * NRELS + (size_t)blockIdx.x * 128) * BDIM;
        Bh = g_relh + bb; Bl = g_rell + bb;
    }

    const uint32_t xorv = (uint32_t)(lane & 7) << 4;
    uint32_t arow[4], brow[2];
    #pragma unroll
    for (int mi = 0; mi < 4; ++mi)
        arow[mi] = (uint32_t)(warp_m * 64 + mi * 16 + (lane & 15)) * 128;
    #pragma unroll
    for (int nj = 0; nj < 2; ++nj)
        brow[nj] = (uint32_t)(warp_n * 32 + nj * 16 + (lane & 7)
                              + ((lane & 16) ? 8 : 0)) * 128;
    const uint32_t ka_h = (uint32_t)((lane >> 4) * 16);
    const uint32_t kb_h = (uint32_t)(((lane >> 3) & 1) * 16);

    float acc[4][4][4] = {};

    load_stage128(Ah, Al, Bh, Bl, 0,  sb,          tid); CP_COMMIT();
    load_stage128(Ah, Al, Bh, Bl, 64, sb + STAGE1, tid); CP_COMMIT();

    for (int c = 0; c < KCHUNKS; ++c) {
        const uint32_t base = sb + (uint32_t)(c % 3) * STAGE1;
        CP_WAIT1();
        __syncthreads();
        #pragma unroll
        for (int ks = 0; ks < 4; ++ks) {
            const uint32_t ka = (uint32_t)(ks * 32) + ka_h;
            const uint32_t kb = (uint32_t)(ks * 32) + kb_h;
            uint32_t ah[4][4], bh_[2][4];
            #pragma unroll
            for (int mi = 0; mi < 4; ++mi) ldsm4(base + arow[mi] + (ka ^ xorv), ah[mi]);
            #pragma unroll
            for (int nj = 0; nj < 2; ++nj) ldsm4(base + 32768 + brow[nj] + (kb ^ xorv), bh_[nj]);
            #pragma unroll
            for (int mi = 0; mi < 4; ++mi)
                #pragma unroll
                for (int ni = 0; ni < 4; ++ni)
                    mma_bf16(acc[mi][ni], ah[mi],
                             bh_[ni >> 1][(ni & 1) * 2], bh_[ni >> 1][(ni & 1) * 2 + 1]);
            uint32_t bl[2][4];
            #pragma unroll
            for (int nj = 0; nj < 2; ++nj) ldsm4(base + 49152 + brow[nj] + (kb ^ xorv), bl[nj]);
            #pragma unroll
            for (int mi = 0; mi < 4; ++mi)
                #pragma unroll
                for (int ni = 0; ni < 4; ++ni)
                    mma_bf16(acc[mi][ni], ah[mi],
                             bl[ni >> 1][(ni & 1) * 2], bl[ni >> 1][(ni & 1) * 2 + 1]);
            uint32_t al[4][4];
            #pragma unroll
            for (int mi = 0; mi < 4; ++mi) ldsm4(base + 16384 + arow[mi] + (ka ^ xorv), al[mi]);
            #pragma unroll
            for (int mi = 0; mi < 4; ++mi)
                #pragma unroll
                for (int ni = 0; ni < 4; ++ni)
                    mma_bf16(acc[mi][ni], al[mi],
                             bh_[ni >> 1][(ni & 1) * 2], bh_[ni >> 1][(ni & 1) * 2 + 1]);
        }
        __syncthreads();
        if (c + 2 < KCHUNKS) {
            load_stage128(Ah, Al, Bh, Bl, (size_t)(c + 2) * 64,
                          sb + (uint32_t)((c + 2) % 3) * STAGE1, tid);
            CP_COMMIT();
        }
    }
    CP_WAIT0();

    const int lr = lane >> 2;
    const int lc = (lane & 3) * 2;

    if (MODE == 0) {
        const int   is_k  = widx & 1;
        const float scale = is_k ? 1.0f : (1.0f / 32.0f);
        const float* bias = (widx == 0) ? b0 : (widx == 1) ? b1 : (widx == 2) ? b2 : b3;
        __nv_bfloat16* outH = (is_k ? g_khi : g_qhi) + (size_t)head * MROWS * BDIM;
        __nv_bfloat16* outL = (is_k ? g_klo : g_qlo) + (size_t)head * MROWS * BDIM;
        const int gm0 = blockIdx.y * 128 + warp_m * 64;
        const int gn0 = bxn * 128 + warp_n * 32;
        #pragma unroll
        for (int mi = 0; mi < 4; ++mi)
            #pragma unroll
            for (int h = 0; h < 2; ++h) {
                const size_t rofs = (size_t)(gm0 + mi * 16 + lr + h * 8) * BDIM;
                #pragma unroll
                for (int ni = 0; ni < 4; ++ni) {
                    const int col = gn0 + ni * 8 + lc;
                    float2 bv = *reinterpret_cast<const float2*>(&bias[col]);
                    float v0 = (acc[mi][ni][h * 2 + 0] + bv.x) * scale;
                    float v1 = (acc[mi][ni][h * 2 + 1] + bv.y) * scale;
                    __nv_bfloat16 h0, h1, l0, l1;
                    split2(v0, h0, l0); split2(v1, h1, l1);
                    *reinterpret_cast<__nv_bfloat162*>(outH + rofs + col)
                        = __halves2bfloat162(h0, h1);
                    *reinterpret_cast<__nv_bfloat162*>(outL + rofs + col)
                        = __halves2bfloat162(l0, l1);
                }
            }
    } else {
        const int gm0 = blockIdx.y * 128 + warp_m * 64;
        const int gn0 = blockIdx.x * 128 + warp_n * 32;
        float* outq = g_qr + (size_t)head * MROWS * NRELS;
        #pragma unroll
        for (int mi = 0; mi < 4; ++mi)
            #pragma unroll
            for (int h = 0; h < 2; ++h) {
                const size_t rofs = (size_t)(gm0 + mi * 16 + lr + h * 8) * NRELS;
                #pragma unroll
                for (int ni = 0; ni < 4; ++ni) {
                    const int col = gn0 + ni * 8 + lc;
                    *reinterpret_cast<float2*>(outq + rofs + col)
                        = make_float2(acc[mi][ni][h * 2], acc[mi][ni][h * 2 + 1]);
                }
            }
    }
}

// ---------------------------------------------------------------------------
// Scores: 128x256 tile, 2-stage. Stage (96KB): Ah@0 Al@16K Bh@32K Bl@64K.
// A = 128 rows, B = 256 rows of [64 bf16] SW128.
// ---------------------------------------------------------------------------
#define STAGE2 98304

__device__ __forceinline__ void load_stage256(
    const __nv_bfloat16* Ah, const __nv_bfloat16* Al,
    const __nv_bfloat16* Bh, const __nv_bfloat16* Bl,
    size_t kelem, uint32_t base, int tid)
{
    #pragma unroll
    for (int m = 0; m < 2; ++m) {
        const char* s = (const char*)((m == 0 ? Ah : Al) + kelem);
        const uint32_t b = base + m * 16384;
        #pragma unroll
        for (int it = 0; it < 4; ++it) {
            const int t = tid + it * 256;
            const int r = t >> 3, c = t & 7;
            const uint32_t off = (uint32_t)(r * 128 + c * 16);
            cp_async16(b + (off ^ ((off >> 3) & 0x70)),
                       s + (size_t)r * (BDIM * 2) + c * 16);
        }
    }
    #pragma unroll
    for (int m = 0; m < 2; ++m) {
        const char* s = (const char*)((m == 0 ? Bh : Bl) + kelem);
        const uint32_t b = base + 32768 + m * 32768;
        #pragma unroll
        for (int it = 0; it < 8; ++it) {
            const int t = tid + it * 256;
            const int r = t >> 3, c = t & 7;
            const uint32_t off = (uint32_t)(r * 128 + c * 16);
            cp_async16(b + (off ^ ((off >> 3) & 0x70)),
                       s + (size_t)r * (BDIM * 2) + c * 16);
        }
    }
}

__global__ __launch_bounds__(256, 1)
void scores256(const int* __restrict__ maskp, float* __restrict__ outF)
{
    extern __shared__ __align__(1024) char smem[];
    const uint32_t sb = smem_u32(smem);
    const int tid  = threadIdx.x;
    const int wid  = tid >> 5;
    const int lane = tid & 31;
    const int warp_m = wid >> 2;       // 0..1 (64 rows)
    const int warp_n = wid & 3;        // 0..3 (64 cols)

    const int z = blockIdx.z, hh = z >> 2, bat = z & 3;
    const size_t ab = ((size_t)hh * MROWS + (size_t)bat * TSEQ
                       + (size_t)blockIdx.y * 128) * BDIM;
    const size_t bb = ((size_t)hh * MROWS + (size_t)bat * TSEQ
                       + (size_t)blockIdx.x * 256) * BDIM;
    const __nv_bfloat16* Ah = g_qhi + ab;
    const __nv_bfloat16* Al = g_qlo + ab;
    const __nv_bfloat16* Bh = g_khi + bb;
    const __nv_bfloat16* Bl = g_klo + bb;

    const uint32_t xorv = (uint32_t)(lane & 7) << 4;
    uint32_t arow[4], brow[4];
    #pragma unroll
    for (int mi = 0; mi < 4; ++mi)
        arow[mi] = (uint32_t)(warp_m * 64 + mi * 16 + (lane & 15)) * 128;
    #pragma unroll
    for (int nj = 0; nj < 4; ++nj)
        brow[nj] = (uint32_t)(warp_n * 64 + nj * 16 + (lane & 7)
                              + ((lane & 16) ? 8 : 0)) * 128;
    const uint32_t ka_h = (uint32_t)((lane >> 4) * 16);
    const uint32_t kb_h = (uint32_t)(((lane >> 3) & 1) * 16);

    float acc[4][8][4] = {};

    load_stage256(Ah, Al, Bh, Bl, 0,  sb,          tid); CP_COMMIT();
    load_stage256(Ah, Al, Bh, Bl, 64, sb + STAGE2, tid); CP_COMMIT();

    for (int c = 0; c < KCHUNKS; ++c) {
        const uint32_t base = sb + (uint32_t)(c & 1) * STAGE2;
        CP_WAIT1();
        __syncthreads();
        #pragma unroll
        for (int ks = 0; ks < 4; ++ks) {
            const uint32_t ka = (uint32_t)(ks * 32) + ka_h;
            const uint32_t kb = (uint32_t)(ks * 32) + kb_h;
            uint32_t ah[4][4], bh_[4][4];
            #pragma unroll
            for (int mi = 0; mi < 4; ++mi) ldsm4(base + arow[mi] + (ka ^ xorv), ah[mi]);
            #pragma unroll
            for (int nj = 0; nj < 4; ++nj) ldsm4(base + 32768 + brow[nj] + (kb ^ xorv), bh_[nj]);
            #pragma unroll
            for (int mi = 0; mi < 4; ++mi)
                #pragma unroll
                for (int ni = 0; ni < 8; ++ni)
                    mma_bf16(acc[mi][ni], ah[mi],
                             bh_[ni >> 1][(ni & 1) * 2], bh_[ni >> 1][(ni & 1) * 2 + 1]);
            uint32_t bl[4][4];
            #pragma unroll
            for (int nj = 0; nj < 4; ++nj) ldsm4(base + 65536 + brow[nj] + (kb ^ xorv), bl[nj]);
            #pragma unroll
            for (int mi = 0; mi < 4; ++mi)
                #pragma unroll
                for (int ni = 0; ni < 8; ++ni)
                    mma_bf16(acc[mi][ni], ah[mi],
                             bl[ni >> 1][(ni & 1) * 2], bl[ni >> 1][(ni & 1) * 2 + 1]);
            uint32_t al[4][4];
            #pragma unroll
            for (int mi = 0; mi < 4; ++mi) ldsm4(base + 16384 + arow[mi] + (ka ^ xorv), al[mi]);
            #pragma unroll
            for (int mi = 0; mi < 4; ++mi)
                #pragma unroll
                for (int ni = 0; ni < 8; ++ni)
                    mma_bf16(acc[mi][ni], al[mi],
                             bh_[ni >> 1][(ni & 1) * 2], bh_[ni >> 1][(ni & 1) * 2 + 1]);
        }
        __syncthreads();
        if (c + 2 < KCHUNKS) {
            load_stage256(Ah, Al, Bh, Bl, (size_t)(c + 2) * 64,
                          sb + (uint32_t)(c & 1) * STAGE2, tid);
            CP_COMMIT();
        }
    }
    CP_WAIT0();
    __syncthreads();

    // Stage qr[128 rows][136] into smem (stride 137)
    float* qrs = reinterpret_cast<float*>(smem);
    const float* qrg = g_qr + ((size_t)hh * MROWS + (size_t)bat * TSEQ
                               + (size_t)blockIdx.y * 128) * NRELS;
    for (int idx = tid; idx < 128 * 34; idx += 256) {
        const int r = idx / 34, c4 = (idx % 34) * 4;
        float4 v = *reinterpret_cast<const float4*>(qrg + (size_t)r * NRELS + c4);
        float* d = qrs + r * 137 + c4;
        d[0] = v.x; d[1] = v.y; d[2] = v.z; d[3] = v.w;
    }
    __syncthreads();

    const int lr = lane >> 2;
    const int lc = (lane & 3) * 2;
    const int gn0 = blockIdx.x * 256 + warp_n * 64;
    #pragma unroll
    for (int mi = 0; mi < 4; ++mi)
        #pragma unroll
        for (int h = 0; h < 2; ++h) {
            const int rloc = warp_m * 64 + mi * 16 + lr + h * 8;     // 0..127
            const int row  = blockIdx.y * 128 + rloc;                // in batch
            const int*  mrow = maskp + ((size_t)bat * TSEQ + row) * TSEQ;
            float*      crow = outF + ((size_t)(hh * 4 + bat) * TSEQ + row) * TSEQ;
            const float* qrow = qrs + rloc * 137;
            #pragma unroll
            for (int ni = 0; ni < 8; ++ni) {
                const int col = gn0 + ni * 8 + lc;
                int2 mv = *reinterpret_cast<const int2*>(mrow + col);
                int d0 = min(max(col + 0 - row, -64), 64) + 64;
                int d1 = min(max(col + 1 - row, -64), 64) + 64;
                float2 o;
                o.x = mv.x ? (acc[mi][ni][h * 2 + 0] + qrow[d0]) : -1e18f;
                o.y = mv.y ? (acc[mi][ni][h * 2 + 1] + qrow[d1]) : -1e18f;
                *reinterpret_cast<float2*>(crow + col) = o;
            }
        }
}

// ---------------------------------------------------------------------------
extern "C" void kernel_launch(void* const* d_in, const int* in_sizes, int n_in,
                              void* d_out, int out_size)
{
    const float* repre  = (const float*)d_in[0];
    const int*   mask   = (const int*)  d_in[1];
    const float* st_Wq  = (const float*)d_in[2];
    const float* st_bq  = (const float*)d_in[3];
    const float* st_Wk  = (const float*)d_in[4];
    const float* st_bk  = (const float*)d_in[5];
    const float* st_rel = (const float*)d_in[6];
    const float* ed_Wq  = (const float*)d_in[7];
    const float* ed_bq  = (const float*)d_in[8];
    const float* ed_Wk  = (const float*)d_in[9];
    const float* ed_bk  = (const float*)d_in[10];
    const float* ed_rel = (const float*)d_in[11];
    float* out = (float*)d_out;

    constexpr int SMEM_G = 3 * STAGE1;   // 196608
    constexpr int SMEM_S = 2 * STAGE2;   // 196608
    cudaFuncSetAttribute(gemm128<0>, cudaFuncAttributeMaxDynamicSharedMemorySize, SMEM_G);
    cudaFuncSetAttribute(gemm128<1>, cudaFuncAttributeMaxDynamicSharedMemorySize, SMEM_G);
    cudaFuncSetAttribute(scores256,  cudaFuncAttributeMaxDynamicSharedMemorySize, SMEM_S);

    // 6 launches total; ncu (-s 5 -c 1) captures launch #6 = scores256.
    split_repre<<<2048, 256>>>(repre);                                   // 1
    relpad_kernel<<<2 * NRELS * BDIM / 256, 256>>>(st_rel, ed_rel);      // 2
    dim3 tb(32, 8), tg(32, 32, 4);
    transpose_split<<<tg, tb>>>(st_Wq, st_Wk, ed_Wq, ed_Wk);             // 3

    dim3 pgrid(32, 64);                                                  // 4 (merged proj)
    gemm128<0><<<pgrid, 256, SMEM_G>>>(st_bq, st_bk, ed_bq, ed_bk);

    dim3 qgrid(2, 64, 2);                                                // 5 (merged qr)
    gemm128<1><<<qgrid, 256, SMEM_G>>>(nullptr, nullptr, nullptr, nullptr);

    dim3 sgrid(8, 16, 8);                                                // 6 (scores)
    scores256<<<sgrid, 256, SMEM_S>>>(mask, out);
}

// round 8
// speedup vs baseline: 1.6342x; 1.6342x over previous
#include <cuda_runtime.h>
#include <cuda_fp16.h>
#include <cstdint>

#define BDIM    1024
#define TSEQ    2048
#define MROWS   8192
#define NRELS   256        // padded rel rows (129 -> 256, zero-filled)
#define KCHUNKS 16         // 1024 / 64

// ---------------------------------------------------------------------------
// Scratch (__device__ globals; no allocations allowed).  All fp16.
// ---------------------------------------------------------------------------
__device__ __half g_xh[(size_t)MROWS * BDIM];     // repre hi
__device__ __half g_xl[(size_t)MROWS * BDIM];     // repre lo
__device__ __half g_wt[4ull * BDIM * BDIM];       // W^T (4 weights, single fp16)
__device__ __half g_qh[2ull * MROWS * BDIM];      // q raw (unscaled) hi
__device__ __half g_ql[2ull * MROWS * BDIM];      // q raw lo
__device__ __half g_kh[2ull * MROWS * BDIM];      // k (single fp16)
__device__ __half g_relh[2ull * NRELS * BDIM];    // rel (single fp16)
__device__ float  g_qr [2ull * MROWS * NRELS];    // qr (scaled by 1/32)

// ---------------------------------------------------------------------------
// Helpers (baseline PTX only: cp.async / ldmatrix / mma.sync)
// ---------------------------------------------------------------------------
__device__ __forceinline__ uint32_t smem_u32(const void* p) {
    uint32_t a;
    asm("{ .reg .u64 t; cvta.to.shared.u64 t, %1; cvt.u32.u64 %0, t; }"
        : "=r"(a) : "l"(p));
    return a;
}

__device__ __forceinline__ void cp_async16(uint32_t dst, const void* src) {
    asm volatile("cp.async.cg.shared.global [%0], [%1], 16;\n" :: "r"(dst), "l"(src));
}
#define CP_COMMIT() asm volatile("cp.async.commit_group;\n" ::: "memory")
#define CP_WAIT1()  asm volatile("cp.async.wait_group 1;\n" ::: "memory")
#define CP_WAIT0()  asm volatile("cp.async.wait_group 0;\n" ::: "memory")

__device__ __forceinline__ void ldsm4(uint32_t addr, uint32_t* r) {
    asm volatile("ldmatrix.sync.aligned.m8n8.x4.shared.b16 {%0,%1,%2,%3}, [%4];"
        : "=r"(r[0]), "=r"(r[1]), "=r"(r[2]), "=r"(r[3]) : "r"(addr));
}

__device__ __forceinline__ void mma_f16(float* c, const uint32_t* a,
                                        uint32_t b0, uint32_t b1) {
    asm volatile(
        "mma.sync.aligned.m16n8k16.row.col.f32.f16.f16.f32 "
        "{%0,%1,%2,%3}, {%4,%5,%6,%7}, {%8,%9}, {%0,%1,%2,%3};"
        : "+f"(c[0]), "+f"(c[1]), "+f"(c[2]), "+f"(c[3])
        : "r"(a[0]), "r"(a[1]), "r"(a[2]), "r"(a[3]), "r"(b0), "r"(b1));
}

__device__ __forceinline__ void split2h(float v, __half& h, __half& l) {
    h = __float2half_rn(v);
    l = __float2half_rn(v - __half2float(h));
}

// ---------------------------------------------------------------------------
// Conversion kernels (3 launches)
// ---------------------------------------------------------------------------
__global__ void split_repre(const float* __restrict__ in) {
    const int n4 = MROWS * BDIM / 4;
    for (int i = blockIdx.x * blockDim.x + threadIdx.x; i < n4;
         i += gridDim.x * blockDim.x) {
        float4 v = reinterpret_cast<const float4*>(in)[i];
        __half h0, h1, h2, h3, l0, l1, l2, l3;
        split2h(v.x, h0, l0); split2h(v.y, h1, l1);
        split2h(v.z, h2, l2); split2h(v.w, h3, l3);
        reinterpret_cast<__half2*>(g_xh)[i * 2 + 0] = __halves2half2(h0, h1);
        reinterpret_cast<__half2*>(g_xh)[i * 2 + 1] = __halves2half2(h2, h3);
        reinterpret_cast<__half2*>(g_xl)[i * 2 + 0] = __halves2half2(l0, l1);
        reinterpret_cast<__half2*>(g_xl)[i * 2 + 1] = __halves2half2(l2, l3);
    }
}

// Both heads, single fp16. idx in [0, 2*NRELS*BDIM)
__global__ void relpad_kernel(const float* __restrict__ rel0,
                              const float* __restrict__ rel1) {
    const int idx  = blockIdx.x * 256 + threadIdx.x;
    const int head = idx >> 18;                    // NRELS*BDIM = 2^18
    const int rem  = idx & 0x3FFFF;
    const int r = rem >> 10, c = rem & 1023;
    const float* rel = head ? rel1 : rel0;
    float v = (r < 129) ? rel[r * BDIM + c] : 0.0f;
    g_relh[idx] = __float2half_rn(v);
}

// W [k][n] -> Wt [n][k] fp16. block(32,8), grid(32,32,4)
__global__ void transpose_w(const float* __restrict__ W0, const float* __restrict__ W1,
                            const float* __restrict__ W2, const float* __restrict__ W3) {
    __shared__ float t[32][33];
    const int widx = blockIdx.z;
    const float* W = (widx == 0) ? W0 : (widx == 1) ? W1 : (widx == 2) ? W2 : W3;
    const int n0 = blockIdx.x * 32, k0 = blockIdx.y * 32;
    for (int i = threadIdx.y; i < 32; i += 8)
        t[i][threadIdx.x] = W[(size_t)(k0 + i) * BDIM + n0 + threadIdx.x];
    __syncthreads();
    __half* th = g_wt + (size_t)widx * BDIM * BDIM;
    for (int i = threadIdx.y; i < 32; i += 8)
        th[(size_t)(n0 + i) * BDIM + k0 + threadIdx.x] = __float2half_rn(t[threadIdx.x][i]);
}

// ---------------------------------------------------------------------------
// Tile loader: [128 rows][64 fp16] SW128 K-major tile.
// BYTE indexing: global row stride = BDIM*2 bytes, chunk = c*16 bytes.
// ---------------------------------------------------------------------------
template<int PASSES>
__device__ __forceinline__ void load_stage(
    const __half* Ah, const __half* Al, const __half* B,
    size_t kelem, uint32_t base, int tid)
{
    const int NOPS = PASSES + 1;
    const __half* srcs[3] = {Ah + kelem, (PASSES == 2 ? Al : B) + kelem, B + kelem};
    #pragma unroll
    for (int m = 0; m < NOPS; ++m) {
        const char* s = (const char*)srcs[m];
        const uint32_t b = base + m * 16384;
        #pragma unroll
        for (int it = 0; it < 4; ++it) {
            const int t = tid + it * 256;
            const int r = t >> 3, c = t & 7;
            const uint32_t off = (uint32_t)(r * 128 + c * 16);
            cp_async16(b + (off ^ ((off >> 3) & 0x70)),
                       s + (size_t)r * (BDIM * 2) + c * 16);
        }
    }
}

// ---------------------------------------------------------------------------
// Unified 128x128 split-fp16 HMMA GEMM (NT), 2 CTAs/SM.
// PASSES=2 stage (48KB): Ah@0  Al@16K  B@32K ; PASSES=1 stage (32KB): Ah@0 B@16K
// MODE 0: proj (widx = bx>>3)  MODE 1: qr (1-pass)  MODE 2: scores
// ---------------------------------------------------------------------------
template<int MODE>
__global__ __launch_bounds__(256, 2)
void gemm_u(const float* __restrict__ b0, const float* __restrict__ b1,
            const float* __restrict__ b2, const float* __restrict__ b3,
            const int* __restrict__ maskp, float* __restrict__ outF)
{
    constexpr int PASSES = (MODE == 1) ? 1 : 2;
    constexpr uint32_t BOFF = (PASSES == 2) ? 32768u : 16384u;
    constexpr uint32_t STG  = BOFF + 16384u;

    extern __shared__ __align__(1024) char smem[];
    const uint32_t sb = smem_u32(smem);
    const int tid  = threadIdx.x;
    const int wid  = tid >> 5;
    const int lane = tid & 31;
    const int warp_m = wid >> 2;       // 0..1 (64 rows)
    const int warp_n = wid & 3;        // 0..3 (32 cols)

    const __half *Ah = nullptr, *Al = nullptr, *B = nullptr;
    int widx = 0, head = 0, bxn = 0, hh = 0, bat = 0;
    if (MODE == 0) {
        widx = blockIdx.x >> 3;  bxn = blockIdx.x & 7;  head = widx >> 1;
        const size_t ab = (size_t)blockIdx.y * 128 * BDIM;
        Ah = g_xh + ab;  Al = g_xl + ab;
        B  = g_wt + (size_t)widx * BDIM * BDIM + (size_t)bxn * 128 * BDIM;
    } else if (MODE == 1) {
        head = blockIdx.z;
        Ah = g_qh + ((size_t)head * MROWS + (size_t)blockIdx.y * 128) * BDIM;
        B  = g_relh + ((size_t)head * NRELS + (size_t)blockIdx.x * 128) * BDIM;
    } else {
        const int z = blockIdx.z; hh = z >> 2; bat = z & 3;
        const size_t rb = (size_t)hh * MROWS + (size_t)bat * TSEQ;
        Ah = g_qh + (rb + (size_t)blockIdx.y * 128) * BDIM;
        Al = g_ql + (rb + (size_t)blockIdx.y * 128) * BDIM;
        B  = g_kh + (rb + (size_t)blockIdx.x * 128) * BDIM;
    }

    const uint32_t xorv = (uint32_t)(lane & 7) << 4;
    uint32_t arow[4], brow[2];
    #pragma unroll
    for (int mi = 0; mi < 4; ++mi)
        arow[mi] = (uint32_t)(warp_m * 64 + mi * 16 + (lane & 15)) * 128;
    #pragma unroll
    for (int nj = 0; nj < 2; ++nj)
        brow[nj] = (uint32_t)(warp_n * 32 + nj * 16 + (lane & 7)
                              + ((lane & 16) ? 8 : 0)) * 128;
    const uint32_t ka_h = (uint32_t)((lane >> 4) * 16);
    const uint32_t kb_h = (uint32_t)(((lane >> 3) & 1) * 16);

    float acc[4][4][4] = {};

    load_stage<PASSES>(Ah, Al, B, 0,  sb,       tid); CP_COMMIT();
    load_stage<PASSES>(Ah, Al, B, 64, sb + STG, tid); CP_COMMIT();

    for (int c = 0; c < KCHUNKS; ++c) {
        const uint32_t base = sb + (uint32_t)(c & 1) * STG;
        CP_WAIT1();
        __syncthreads();
        #pragma unroll
        for (int ks = 0; ks < 4; ++ks) {
            const uint32_t ka = (uint32_t)(ks * 32) + ka_h;
            const uint32_t kb = (uint32_t)(ks * 32) + kb_h;
            uint32_t ah[4][4], bf[2][4];
            #pragma unroll
            for (int mi = 0; mi < 4; ++mi) ldsm4(base + arow[mi] + (ka ^ xorv), ah[mi]);
            #pragma unroll
            for (int nj = 0; nj < 2; ++nj) ldsm4(base + BOFF + brow[nj] + (kb ^ xorv), bf[nj]);
            #pragma unroll
            for (int mi = 0; mi < 4; ++mi)
                #pragma unroll
                for (int ni = 0; ni < 4; ++ni)
                    mma_f16(acc[mi][ni], ah[mi],
                            bf[ni >> 1][(ni & 1) * 2], bf[ni >> 1][(ni & 1) * 2 + 1]);
            if (PASSES == 2) {
                uint32_t al[4][4];
                #pragma unroll
                for (int mi = 0; mi < 4; ++mi) ldsm4(base + 16384 + arow[mi] + (ka ^ xorv), al[mi]);
                #pragma unroll
                for (int mi = 0; mi < 4; ++mi)
                    #pragma unroll
                    for (int ni = 0; ni < 4; ++ni)
                        mma_f16(acc[mi][ni], al[mi],
                                bf[ni >> 1][(ni & 1) * 2], bf[ni >> 1][(ni & 1) * 2 + 1]);
            }
        }
        __syncthreads();
        if (c + 2 < KCHUNKS) {
            load_stage<PASSES>(Ah, Al, B, (size_t)(c + 2) * 64,
                               sb + (uint32_t)(c & 1) * STG, tid);
            CP_COMMIT();
        }
    }
    CP_WAIT0();

    const int lr = lane >> 2;
    const int lc = (lane & 3) * 2;
    constexpr float inv32 = 1.0f / 32.0f;

    if (MODE == 0) {
        const int is_k = widx & 1;
        const float* bias = (widx == 0) ? b0 : (widx == 1) ? b1 : (widx == 2) ? b2 : b3;
        const int gm0 = blockIdx.y * 128 + warp_m * 64;
        const int gn0 = bxn * 128 + warp_n * 32;
        if (is_k) {
            __half* outK = g_kh + (size_t)head * MROWS * BDIM;
            #pragma unroll
            for (int mi = 0; mi < 4; ++mi)
                #pragma unroll
                for (int h = 0; h < 2; ++h) {
                    const size_t rofs = (size_t)(gm0 + mi * 16 + lr + h * 8) * BDIM;
                    #pragma unroll
                    for (int ni = 0; ni < 4; ++ni) {
                        const int col = gn0 + ni * 8 + lc;
                        float2 bv = *reinterpret_cast<const float2*>(&bias[col]);
                        *reinterpret_cast<__half2*>(outK + rofs + col) = __halves2half2(
                            __float2half_rn(acc[mi][ni][h * 2 + 0] + bv.x),
                            __float2half_rn(acc[mi][ni][h * 2 + 1] + bv.y));
                    }
                }
        } else {
            __half* outH = g_qh + (size_t)head * MROWS * BDIM;
            __half* outL = g_ql + (size_t)head * MROWS * BDIM;
            #pragma unroll
            for (int mi = 0; mi < 4; ++mi)
                #pragma unroll
                for (int h = 0; h < 2; ++h) {
                    const size_t rofs = (size_t)(gm0 + mi * 16 + lr + h * 8) * BDIM;
                    #pragma unroll
                    for (int ni = 0; ni < 4; ++ni) {
                        const int col = gn0 + ni * 8 + lc;
                        float2 bv = *reinterpret_cast<const float2*>(&bias[col]);
                        __half h0, h1, l0, l1;
                        split2h(acc[mi][ni][h * 2 + 0] + bv.x, h0, l0);
                        split2h(acc[mi][ni][h * 2 + 1] + bv.y, h1, l1);
                        *reinterpret_cast<__half2*>(outH + rofs + col) = __halves2half2(h0, h1);
                        *reinterpret_cast<__half2*>(outL + rofs + col) = __halves2half2(l0, l1);
                    }
                }
        }
    } else if (MODE == 1) {
        const int gm0 = blockIdx.y * 128 + warp_m * 64;
        const int gn0 = blockIdx.x * 128 + warp_n * 32;
        float* outq = g_qr + (size_t)head * MROWS * NRELS;
        #pragma unroll
        for (int mi = 0; mi < 4; ++mi)
            #pragma unroll
            for (int h = 0; h < 2; ++h) {
                const size_t rofs = (size_t)(gm0 + mi * 16 + lr + h * 8) * NRELS;
                #pragma unroll
                for (int ni = 0; ni < 4; ++ni) {
                    const int col = gn0 + ni * 8 + lc;
                    *reinterpret_cast<float2*>(outq + rofs + col)
                        = make_float2(acc[mi][ni][h * 2] * inv32,
                                      acc[mi][ni][h * 2 + 1] * inv32);
                }
            }
    } else {
        __syncthreads();
        // Stage qr[128 rows][136] into smem with stride 137 (conflict-spread)
        float* qrs = reinterpret_cast<float*>(smem);
        const float* qrg = g_qr + ((size_t)hh * MROWS + (size_t)bat * TSEQ
                                   + (size_t)blockIdx.y * 128) * NRELS;
        for (int idx = tid; idx < 128 * 34; idx += 256) {
            const int r = idx / 34, c4 = (idx % 34) * 4;
            float4 v = *reinterpret_cast<const float4*>(qrg + (size_t)r * NRELS + c4);
            float* d = qrs + r * 137 + c4;
            d[0] = v.x; d[1] = v.y; d[2] = v.z; d[3] = v.w;
        }
        __syncthreads();

        const int gn0 = blockIdx.x * 128 + warp_n * 32;
        #pragma unroll
        for (int mi = 0; mi < 4; ++mi)
            #pragma unroll
            for (int h = 0; h < 2; ++h) {
                const int rloc = warp_m * 64 + mi * 16 + lr + h * 8;   // 0..127
                const int row  = blockIdx.y * 128 + rloc;              // in batch
                const int*  mrow = maskp + ((size_t)bat * TSEQ + row) * TSEQ;
                float*      crow = outF + ((size_t)(hh * 4 + bat) * TSEQ + row) * TSEQ;
                const float* qrow = qrs + rloc * 137;
                #pragma unroll
                for (int ni = 0; ni < 4; ++ni) {
                    const int col = gn0 + ni * 8 + lc;
                    int2 mv = *reinterpret_cast<const int2*>(mrow + col);
                    int d0 = min(max(col + 0 - row, -64), 64) + 64;
                    int d1 = min(max(col + 1 - row, -64), 64) + 64;
                    float2 o;
                    o.x = mv.x ? (acc[mi][ni][h * 2 + 0] * inv32 + qrow[d0]) : -1e18f;
                    o.y = mv.y ? (acc[mi][ni][h * 2 + 1] * inv32 + qrow[d1]) : -1e18f;
                    *reinterpret_cast<float2*>(crow + col) = o;
                }
            }
    }
}

// ---------------------------------------------------------------------------
extern "C" void kernel_launch(void* const* d_in, const int* in_sizes, int n_in,
                              void* d_out, int out_size)
{
    const float* repre  = (const float*)d_in[0];
    const int*   mask   = (const int*)  d_in[1];
    const float* st_Wq  = (const float*)d_in[2];
    const float* st_bq  = (const float*)d_in[3];
    const float* st_Wk  = (const float*)d_in[4];
    const float* st_bk  = (const float*)d_in[5];
    const float* st_rel = (const float*)d_in[6];
    const float* ed_Wq  = (const float*)d_in[7];
    const float* ed_bq  = (const float*)d_in[8];
    const float* ed_Wk  = (const float*)d_in[9];
    const float* ed_bk  = (const float*)d_in[10];
    const float* ed_rel = (const float*)d_in[11];
    float* out = (float*)d_out;

    constexpr int SMEM2 = 2 * (3 * 16384);   // 98304 (2-pass: Ah,Al,B x2 stages)
    constexpr int SMEM1 = 2 * (2 * 16384);   // 65536 (1-pass: Ah,B x2 stages)
    cudaFuncSetAttribute(gemm_u<0>, cudaFuncAttributeMaxDynamicSharedMemorySize, SMEM2);
    cudaFuncSetAttribute(gemm_u<1>, cudaFuncAttributeMaxDynamicSharedMemorySize, SMEM1);
    cudaFuncSetAttribute(gemm_u<2>, cudaFuncAttributeMaxDynamicSharedMemorySize, SMEM2);

    // 6 launches; ncu (-s 5 -c 1) captures launch #6 = scores (gemm_u<2>).
    split_repre<<<2048, 256>>>(repre);                                   // 1
    relpad_kernel<<<2 * NRELS * BDIM / 256, 256>>>(st_rel, ed_rel);      // 2
    dim3 tb(32, 8), tg(32, 32, 4);
    transpose_w<<<tg, tb>>>(st_Wq, st_Wk, ed_Wq, ed_Wk);                 // 3

    dim3 pgrid(32, 64);                                                  // 4 proj
    gemm_u<0><<<pgrid, 256, SMEM2>>>(st_bq, st_bk, ed_bq, ed_bk, nullptr, nullptr);

    dim3 qgrid(2, 64, 2);                                                // 5 qr
    gemm_u<1><<<qgrid, 256, SMEM1>>>(nullptr, nullptr, nullptr, nullptr, nullptr, nullptr);

    dim3 sgrid(16, 16, 8);                                               // 6 scores
    gemm_u<2><<<sgrid, 256, SMEM2>>>(nullptr, nullptr, nullptr, nullptr, mask, out);
}

// round 9
// speedup vs baseline: 3.0284x; 1.8532x over previous
#include <cuda_runtime.h>
#include <cuda_fp16.h>
#include <cstdint>

#define BDIM    1024
#define TSEQ    2048
#define MROWS   8192
#define NRELS   256        // padded rel rows (129 -> 256, zero-filled)
#define KCHUNKS 16         // 1024 / 64

// ---------------------------------------------------------------------------
// Scratch (__device__ globals; no allocations allowed).  All fp16.
// ---------------------------------------------------------------------------
__device__ __half g_xh[(size_t)MROWS * BDIM];     // repre (single fp16)
__device__ __half g_wt[4ull * BDIM * BDIM];       // W^T (4 weights, single fp16)
__device__ __half g_qh[2ull * MROWS * BDIM];      // q raw (unscaled) hi
__device__ __half g_ql[2ull * MROWS * BDIM];      // q raw lo
__device__ __half g_kh[2ull * MROWS * BDIM];      // k (single fp16)
__device__ __half g_relh[2ull * NRELS * BDIM];    // rel (single fp16)
__device__ float  g_qr [2ull * MROWS * NRELS];    // qr (scaled by 1/32)

// ---------------------------------------------------------------------------
// Helpers (baseline PTX only: cp.async / ldmatrix / mma.sync)
// ---------------------------------------------------------------------------
__device__ __forceinline__ uint32_t smem_u32(const void* p) {
    uint32_t a;
    asm("{ .reg .u64 t; cvta.to.shared.u64 t, %1; cvt.u32.u64 %0, t; }"
        : "=r"(a) : "l"(p));
    return a;
}

__device__ __forceinline__ void cp_async16(uint32_t dst, const void* src) {
    asm volatile("cp.async.cg.shared.global [%0], [%1], 16;\n" :: "r"(dst), "l"(src));
}
#define CP_COMMIT() asm volatile("cp.async.commit_group;\n" ::: "memory")
#define CP_WAIT1()  asm volatile("cp.async.wait_group 1;\n" ::: "memory")
#define CP_WAIT0()  asm volatile("cp.async.wait_group 0;\n" ::: "memory")

__device__ __forceinline__ void ldsm4(uint32_t addr, uint32_t* r) {
    asm volatile("ldmatrix.sync.aligned.m8n8.x4.shared.b16 {%0,%1,%2,%3}, [%4];"
        : "=r"(r[0]), "=r"(r[1]), "=r"(r[2]), "=r"(r[3]) : "r"(addr));
}

__device__ __forceinline__ void mma_f16(float* c, const uint32_t* a,
                                        uint32_t b0, uint32_t b1) {
    asm volatile(
        "mma.sync.aligned.m16n8k16.row.col.f32.f16.f16.f32 "
        "{%0,%1,%2,%3}, {%4,%5,%6,%7}, {%8,%9}, {%0,%1,%2,%3};"
        : "+f"(c[0]), "+f"(c[1]), "+f"(c[2]), "+f"(c[3])
        : "r"(a[0]), "r"(a[1]), "r"(a[2]), "r"(a[3]), "r"(b0), "r"(b1));
}

__device__ __forceinline__ void split2h(float v, __half& h, __half& l) {
    h = __float2half_rn(v);
    l = __float2half_rn(v - __half2float(h));
}

// ---------------------------------------------------------------------------
// Conversion kernels (3 launches)
// ---------------------------------------------------------------------------
__global__ void conv_repre(const float* __restrict__ in) {
    const int n4 = MROWS * BDIM / 4;
    for (int i = blockIdx.x * blockDim.x + threadIdx.x; i < n4;
         i += gridDim.x * blockDim.x) {
        float4 v = reinterpret_cast<const float4*>(in)[i];
        reinterpret_cast<__half2*>(g_xh)[i * 2 + 0]
            = __halves2half2(__float2half_rn(v.x), __float2half_rn(v.y));
        reinterpret_cast<__half2*>(g_xh)[i * 2 + 1]
            = __halves2half2(__float2half_rn(v.z), __float2half_rn(v.w));
    }
}

// Both heads, single fp16. idx in [0, 2*NRELS*BDIM)
__global__ void relpad_kernel(const float* __restrict__ rel0,
                              const float* __restrict__ rel1) {
    const int idx  = blockIdx.x * 256 + threadIdx.x;
    const int head = idx >> 18;                    // NRELS*BDIM = 2^18
    const int rem  = idx & 0x3FFFF;
    const int r = rem >> 10, c = rem & 1023;
    const float* rel = head ? rel1 : rel0;
    float v = (r < 129) ? rel[r * BDIM + c] : 0.0f;
    g_relh[idx] = __float2half_rn(v);
}

// W [k][n] -> Wt [n][k] fp16. block(32,8), grid(32,32,4)
__global__ void transpose_w(const float* __restrict__ W0, const float* __restrict__ W1,
                            const float* __restrict__ W2, const float* __restrict__ W3) {
    __shared__ float t[32][33];
    const int widx = blockIdx.z;
    const float* W = (widx == 0) ? W0 : (widx == 1) ? W1 : (widx == 2) ? W2 : W3;
    const int n0 = blockIdx.x * 32, k0 = blockIdx.y * 32;
    for (int i = threadIdx.y; i < 32; i += 8)
        t[i][threadIdx.x] = W[(size_t)(k0 + i) * BDIM + n0 + threadIdx.x];
    __syncthreads();
    __half* th = g_wt + (size_t)widx * BDIM * BDIM;
    for (int i = threadIdx.y; i < 32; i += 8)
        th[(size_t)(n0 + i) * BDIM + k0 + threadIdx.x] = __float2half_rn(t[threadIdx.x][i]);
}

// ---------------------------------------------------------------------------
// Tile loader: [128 rows][64 fp16] SW128 K-major tile.
// BYTE indexing: global row stride = BDIM*2 bytes, chunk = c*16 bytes.
// ---------------------------------------------------------------------------
template<int PASSES>
__device__ __forceinline__ void load_stage(
    const __half* Ah, const __half* Al, const __half* B,
    size_t kelem, uint32_t base, int tid)
{
    const int NOPS = PASSES + 1;
    const __half* srcs[3] = {Ah + kelem, (PASSES == 2 ? Al : B) + kelem, B + kelem};
    #pragma unroll
    for (int m = 0; m < NOPS; ++m) {
        const char* s = (const char*)srcs[m];
        const uint32_t b = base + m * 16384;
        #pragma unroll
        for (int it = 0; it < 4; ++it) {
            const int t = tid + it * 256;
            const int r = t >> 3, c = t & 7;
            const uint32_t off = (uint32_t)(r * 128 + c * 16);
            cp_async16(b + (off ^ ((off >> 3) & 0x70)),
                       s + (size_t)r * (BDIM * 2) + c * 16);
        }
    }
}

// ---------------------------------------------------------------------------
// Unified 128x128 fp16 HMMA GEMM (NT), 2 CTAs/SM.
// MODE 0: proj (1-pass)  MODE 1: qr (1-pass)  MODE 2: scores (2-pass split q)
// 2-pass stage (48KB): Ah@0 Al@16K B@32K ; 1-pass stage (32KB): A@0 B@16K
// ---------------------------------------------------------------------------
template<int MODE>
__global__ __launch_bounds__(256, 2)
void gemm_u(const float* __restrict__ b0, const float* __restrict__ b1,
            const float* __restrict__ b2, const float* __restrict__ b3,
            const int* __restrict__ maskp, float* __restrict__ outF)
{
    constexpr int PASSES = (MODE == 2) ? 2 : 1;
    constexpr uint32_t BOFF = (PASSES == 2) ? 32768u : 16384u;
    constexpr uint32_t STG  = BOFF + 16384u;

    extern __shared__ __align__(1024) char smem[];
    const uint32_t sb = smem_u32(smem);
    const int tid  = threadIdx.x;
    const int wid  = tid >> 5;
    const int lane = tid & 31;
    const int warp_m = wid >> 2;       // 0..1 (64 rows)
    const int warp_n = wid & 3;        // 0..3 (32 cols)

    const __half *Ah = nullptr, *Al = nullptr, *B = nullptr;
    int widx = 0, head = 0, bxn = 0, hh = 0, bat = 0;
    if (MODE == 0) {
        widx = blockIdx.x >> 3;  bxn = blockIdx.x & 7;  head = widx >> 1;
        Ah = g_xh + (size_t)blockIdx.y * 128 * BDIM;
        B  = g_wt + (size_t)widx * BDIM * BDIM + (size_t)bxn * 128 * BDIM;
    } else if (MODE == 1) {
        head = blockIdx.z;
        Ah = g_qh + ((size_t)head * MROWS + (size_t)blockIdx.y * 128) * BDIM;
        B  = g_relh + ((size_t)head * NRELS + (size_t)blockIdx.x * 128) * BDIM;
    } else {
        const int z = blockIdx.z; hh = z >> 2; bat = z & 3;
        const size_t rb = (size_t)hh * MROWS + (size_t)bat * TSEQ;
        Ah = g_qh + (rb + (size_t)blockIdx.y * 128) * BDIM;
        Al = g_ql + (rb + (size_t)blockIdx.y * 128) * BDIM;
        B  = g_kh + (rb + (size_t)blockIdx.x * 128) * BDIM;
    }

    const uint32_t xorv = (uint32_t)(lane & 7) << 4;
    uint32_t arow[4], brow[2];
    #pragma unroll
    for (int mi = 0; mi < 4; ++mi)
        arow[mi] = (uint32_t)(warp_m * 64 + mi * 16 + (lane & 15)) * 128;
    #pragma unroll
    for (int nj = 0; nj < 2; ++nj)
        brow[nj] = (uint32_t)(warp_n * 32 + nj * 16 + (lane & 7)
                              + ((lane & 16) ? 8 : 0)) * 128;
    const uint32_t ka_h = (uint32_t)((lane >> 4) * 16);
    const uint32_t kb_h = (uint32_t)(((lane >> 3) & 1) * 16);

    float acc[4][4][4] = {};

    load_stage<PASSES>(Ah, Al, B, 0,  sb,       tid); CP_COMMIT();
    load_stage<PASSES>(Ah, Al, B, 64, sb + STG, tid); CP_COMMIT();

    for (int c = 0; c < KCHUNKS; ++c) {
        const uint32_t base = sb + (uint32_t)(c & 1) * STG;
        CP_WAIT1();
        __syncthreads();
        #pragma unroll
        for (int ks = 0; ks < 4; ++ks) {
            const uint32_t ka = (uint32_t)(ks * 32) + ka_h;
            const uint32_t kb = (uint32_t)(ks * 32) + kb_h;
            uint32_t ah[4][4], bf[2][4];
            #pragma unroll
            for (int mi = 0; mi < 4; ++mi) ldsm4(base + arow[mi] + (ka ^ xorv), ah[mi]);
            #pragma unroll
            for (int nj = 0; nj < 2; ++nj) ldsm4(base + BOFF + brow[nj] + (kb ^ xorv), bf[nj]);
            #pragma unroll
            for (int mi = 0; mi < 4; ++mi)
                #pragma unroll
                for (int ni = 0; ni < 4; ++ni)
                    mma_f16(acc[mi][ni], ah[mi],
                            bf[ni >> 1][(ni & 1) * 2], bf[ni >> 1][(ni & 1) * 2 + 1]);
            if (PASSES == 2) {
                uint32_t al[4][4];
                #pragma unroll
                for (int mi = 0; mi < 4; ++mi) ldsm4(base + 16384 + arow[mi] + (ka ^ xorv), al[mi]);
                #pragma unroll
                for (int mi = 0; mi < 4; ++mi)
                    #pragma unroll
                    for (int ni = 0; ni < 4; ++ni)
                        mma_f16(acc[mi][ni], al[mi],
                                bf[ni >> 1][(ni & 1) * 2], bf[ni >> 1][(ni & 1) * 2 + 1]);
            }
        }
        __syncthreads();
        if (c + 2 < KCHUNKS) {
            load_stage<PASSES>(Ah, Al, B, (size_t)(c + 2) * 64,
                               sb + (uint32_t)(c & 1) * STG, tid);
            CP_COMMIT();
        }
    }
    CP_WAIT0();

    const int lr = lane >> 2;
    const int lc = (lane & 3) * 2;
    constexpr float inv32 = 1.0f / 32.0f;

    if (MODE == 0) {
        const int is_k = widx & 1;
        const float* bias = (widx == 0) ? b0 : (widx == 1) ? b1 : (widx == 2) ? b2 : b3;
        const int gm0 = blockIdx.y * 128 + warp_m * 64;
        const int gn0 = bxn * 128 + warp_n * 32;
        if (is_k) {
            __half* outK = g_kh + (size_t)head * MROWS * BDIM;
            #pragma unroll
            for (int mi = 0; mi < 4; ++mi)
                #pragma unroll
                for (int h = 0; h < 2; ++h) {
                    const size_t rofs = (size_t)(gm0 + mi * 16 + lr + h * 8) * BDIM;
                    #pragma unroll
                    for (int ni = 0; ni < 4; ++ni) {
                        const int col = gn0 + ni * 8 + lc;
                        float2 bv = *reinterpret_cast<const float2*>(&bias[col]);
                        *reinterpret_cast<__half2*>(outK + rofs + col) = __halves2half2(
                            __float2half_rn(acc[mi][ni][h * 2 + 0] + bv.x),
                            __float2half_rn(acc[mi][ni][h * 2 + 1] + bv.y));
                    }
                }
        } else {
            __half* outH = g_qh + (size_t)head * MROWS * BDIM;
            __half* outL = g_ql + (size_t)head * MROWS * BDIM;
            #pragma unroll
            for (int mi = 0; mi < 4; ++mi)
                #pragma unroll
                for (int h = 0; h < 2; ++h) {
                    const size_t rofs = (size_t)(gm0 + mi * 16 + lr + h * 8) * BDIM;
                    #pragma unroll
                    for (int ni = 0; ni < 4; ++ni) {
                        const int col = gn0 + ni * 8 + lc;
                        float2 bv = *reinterpret_cast<const float2*>(&bias[col]);
                        __half h0, h1, l0, l1;
                        split2h(acc[mi][ni][h * 2 + 0] + bv.x, h0, l0);
                        split2h(acc[mi][ni][h * 2 + 1] + bv.y, h1, l1);
                        *reinterpret_cast<__half2*>(outH + rofs + col) = __halves2half2(h0, h1);
                        *reinterpret_cast<__half2*>(outL + rofs + col) = __halves2half2(l0, l1);
                    }
                }
        }
    } else if (MODE == 1) {
        const int gm0 = blockIdx.y * 128 + warp_m * 64;
        const int gn0 = blockIdx.x * 128 + warp_n * 32;
        float* outq = g_qr + (size_t)head * MROWS * NRELS;
        #pragma unroll
        for (int mi = 0; mi < 4; ++mi)
            #pragma unroll
            for (int h = 0; h < 2; ++h) {
                const size_t rofs = (size_t)(gm0 + mi * 16 + lr + h * 8) * NRELS;
                #pragma unroll
                for (int ni = 0; ni < 4; ++ni) {
                    const int col = gn0 + ni * 8 + lc;
                    *reinterpret_cast<float2*>(outq + rofs + col)
                        = make_float2(acc[mi][ni][h * 2] * inv32,
                                      acc[mi][ni][h * 2 + 1] * inv32);
                }
            }
    } else {
        __syncthreads();
        // Stage qr[128 rows][136] into smem with stride 137 (conflict-spread)
        float* qrs = reinterpret_cast<float*>(smem);
        const float* qrg = g_qr + ((size_t)hh * MROWS + (size_t)bat * TSEQ
                                   + (size_t)blockIdx.y * 128) * NRELS;
        for (int idx = tid; idx < 128 * 34; idx += 256) {
            const int r = idx / 34, c4 = (idx % 34) * 4;
            float4 v = *reinterpret_cast<const float4*>(qrg + (size_t)r * NRELS + c4);
            float* d = qrs + r * 137 + c4;
            d[0] = v.x; d[1] = v.y; d[2] = v.z; d[3] = v.w;
        }
        __syncthreads();

        const int gn0 = blockIdx.x * 128 + warp_n * 32;
        #pragma unroll
        for (int mi = 0; mi < 4; ++mi)
            #pragma unroll
            for (int h = 0; h < 2; ++h) {
                const int rloc = warp_m * 64 + mi * 16 + lr + h * 8;   // 0..127
                const int row  = blockIdx.y * 128 + rloc;              // in batch
                const int*  mrow = maskp + ((size_t)bat * TSEQ + row) * TSEQ;
                float*      crow = outF + ((size_t)(hh * 4 + bat) * TSEQ + row) * TSEQ;
                const float* qrow = qrs + rloc * 137;
                #pragma unroll
                for (int ni = 0; ni < 4; ++ni) {
                    const int col = gn0 + ni * 8 + lc;
                    int2 mv = *reinterpret_cast<const int2*>(mrow + col);
                    int d0 = min(max(col + 0 - row, -64), 64) + 64;
                    int d1 = min(max(col + 1 - row, -64), 64) + 64;
                    float2 o;
                    o.x = mv.x ? (acc[mi][ni][h * 2 + 0] * inv32 + qrow[d0]) : -1e18f;
                    o.y = mv.y ? (acc[mi][ni][h * 2 + 1] * inv32 + qrow[d1]) : -1e18f;
                    *reinterpret_cast<float2*>(crow + col) = o;
                }
            }
    }
}

// ---------------------------------------------------------------------------
extern "C" void kernel_launch(void* const* d_in, const int* in_sizes, int n_in,
                              void* d_out, int out_size)
{
    const float* repre  = (const float*)d_in[0];
    const int*   mask   = (const int*)  d_in[1];
    const float* st_Wq  = (const float*)d_in[2];
    const float* st_bq  = (const float*)d_in[3];
    const float* st_Wk  = (const float*)d_in[4];
    const float* st_bk  = (const float*)d_in[5];
    const float* st_rel = (const float*)d_in[6];
    const float* ed_Wq  = (const float*)d_in[7];
    const float* ed_bq  = (const float*)d_in[8];
    const float* ed_Wk  = (const float*)d_in[9];
    const float* ed_bk  = (const float*)d_in[10];
    const float* ed_rel = (const float*)d_in[11];
    float* out = (float*)d_out;

    constexpr int SMEM2 = 2 * (3 * 16384);   // 98304 (2-pass: Ah,Al,B x2 stages)
    constexpr int SMEM1 = 2 * (2 * 16384);   // 65536 (1-pass: A,B x2 stages)
    cudaFuncSetAttribute(gemm_u<0>, cudaFuncAttributeMaxDynamicSharedMemorySize, SMEM1);
    cudaFuncSetAttribute(gemm_u<1>, cudaFuncAttributeMaxDynamicSharedMemorySize, SMEM1);
    cudaFuncSetAttribute(gemm_u<2>, cudaFuncAttributeMaxDynamicSharedMemorySize, SMEM2);

    // 6 launches; ncu (-s 5 -c 1) captures launch #6 = scores (gemm_u<2>).
    conv_repre<<<2048, 256>>>(repre);                                    // 1
    relpad_kernel<<<2 * NRELS * BDIM / 256, 256>>>(st_rel, ed_rel);      // 2
    dim3 tb(32, 8), tg(32, 32, 4);
    transpose_w<<<tg, tb>>>(st_Wq, st_Wk, ed_Wq, ed_Wk);                 // 3

    dim3 pgrid(32, 64);                                                  // 4 proj
    gemm_u<0><<<pgrid, 256, SMEM1>>>(st_bq, st_bk, ed_bq, ed_bk, nullptr, nullptr);

    dim3 qgrid(2, 64, 2);                                                // 5 qr
    gemm_u<1><<<qgrid, 256, SMEM1>>>(nullptr, nullptr, nullptr, nullptr, nullptr, nullptr);

    dim3 sgrid(16, 16, 8);                                               // 6 scores
    gemm_u<2><<<sgrid, 256, SMEM2>>>(nullptr, nullptr, nullptr, nullptr, mask, out);
}